// round 4
// baseline (speedup 1.0000x reference)
#include <cuda_runtime.h>

#define T_DIM   32
#define N_NODES 10000
#define E_EDGES 160000
#define F_DIM   64
#define TN      (T_DIM * N_NODES)
#define CAP     64                      // max in-degree bucket capacity

typedef unsigned long long ull;

// ---- packed f32x2 helpers (FFMA2 is PTX-only; ptxas never auto-fuses) ----
__device__ __forceinline__ ull pack2(float lo, float hi) {
    ull r; asm("mov.b64 %0, {%1, %2};" : "=l"(r) : "f"(lo), "f"(hi)); return r;
}
__device__ __forceinline__ float2 unpack2(ull v) {
    float2 r; asm("mov.b64 {%0, %1}, %2;" : "=f"(r.x), "=f"(r.y) : "l"(v)); return r;
}
__device__ __forceinline__ ull fma2(ull a, ull b, ull c) {
    ull d; asm("fma.rn.f32x2 %0, %1, %2, %3;" : "=l"(d) : "l"(a), "l"(b), "l"(c)); return d;
}
__device__ __forceinline__ ull add2(ull a, ull b) {
    ull d; asm("add.rn.f32x2 %0, %1, %2;" : "=l"(d) : "l"(a), "l"(b)); return d;
}

// -------- device scratch (allocation-free rule: __device__ globals) --------
// Static init: if edges are int64 this is never written (stays 1 forever);
// if int32, every launch re-writes 0. Deterministic across graph replays.
__device__ int   g_i64flag = 1;
__device__ float g_deg[N_NODES];
__device__ int   g_count[N_NODES];
__device__ int2  g_csr[N_NODES * CAP];               // {src, norm_as_int}, 5.1 MB
__device__ float g_bufA[(size_t)TN * F_DIM];         // 81.92 MB
__device__ float g_bufB[(size_t)TN * F_DIM];         // 81.92 MB

__device__ __forceinline__ int edge_src(const void* ei, int e) {
    return g_i64flag ? (int)((const long long*)ei)[e] : ((const int*)ei)[e];
}
__device__ __forceinline__ int edge_dst(const void* ei, int e) {
    return g_i64flag ? (int)((const long long*)ei)[E_EDGES + e]
                     : ((const int*)ei)[E_EDGES + e];
}

// -------- launch 0: dtype detect + zero deg/count --------
// Reading first E entries as int64 is in-bounds for either dtype (int32
// buffer is exactly 8E bytes). If data is int32, some packed pair lands
// outside [0, N) with overwhelming probability -> flag forced to 0.
__global__ void k_detect_init(const void* __restrict__ ei) {
    int e = blockIdx.x * blockDim.x + threadIdx.x;
    if (e < N_NODES) { g_deg[e] = 0.f; g_count[e] = 0; }
    if (e < E_EDGES) {
        long long v = ((const long long*)ei)[e];
        if (v < 0 || v >= N_NODES) g_i64flag = 0;
    }
}

// -------- launch 1: weighted in-degree --------
__global__ void k_hist(const void* __restrict__ ei, const float* __restrict__ ew) {
    int e = blockIdx.x * blockDim.x + threadIdx.x;
    if (e < E_EDGES) atomicAdd(&g_deg[edge_dst(ei, e)], ew[e]);
}

// -------- launch 2: fill per-dst buckets, dinv computed inline --------
__global__ void k_fill(const void* __restrict__ ei, const float* __restrict__ ew) {
    int e = blockIdx.x * blockDim.x + threadIdx.x;
    if (e < E_EDGES) {
        int src = edge_src(ei, e);
        int dst = edge_dst(ei, e);
        float ds = g_deg[src], dd = g_deg[dst];
        float is = (ds > 0.f) ? rsqrtf(ds) : 0.f;
        float id = (dd > 0.f) ? rsqrtf(dd) : 0.f;
        float nm = is * ew[e] * id;
        int pos = atomicAdd(&g_count[dst], 1);
        if (pos < CAP)
            g_csr[dst * CAP + pos] = make_int2(src, __float_as_int(nm));
    }
}

// -------- aggregation: one warp per (t, node), t-MAJOR (active gather window
// = one 2.56 MB t-slice, L2-resident). Pull over buckets, no atomics. --------
__global__ void __launch_bounds__(256) k_agg(const float* __restrict__ in,
                                             float* __restrict__ out) {
    int wg   = (blockIdx.x * blockDim.x + threadIdx.x) >> 5;
    int lane = threadIdx.x & 31;
    if (wg >= TN) return;
    int t    = wg / N_NODES;
    int node = wg - t * N_NODES;

    const int2* row = &g_csr[node * CAP];
    int cnt = g_count[node];
    if (cnt > CAP) cnt = CAP;

    const ull* base = (const ull*)(in + (size_t)t * (N_NODES * F_DIM));
    ull a0 = 0ull, a1 = 0ull, a2 = 0ull, a3 = 0ull;

    int e = 0;
    int n8 = cnt & ~7;
    for (; e < n8; e += 8) {
        int2 s0 = __ldg(&row[e]);     int2 s1 = __ldg(&row[e + 1]);
        int2 s2 = __ldg(&row[e + 2]); int2 s3 = __ldg(&row[e + 3]);
        int2 s4 = __ldg(&row[e + 4]); int2 s5 = __ldg(&row[e + 5]);
        int2 s6 = __ldg(&row[e + 6]); int2 s7 = __ldg(&row[e + 7]);
        ull v0 = __ldg(base + (size_t)s0.x * 32 + lane);
        ull v1 = __ldg(base + (size_t)s1.x * 32 + lane);
        ull v2 = __ldg(base + (size_t)s2.x * 32 + lane);
        ull v3 = __ldg(base + (size_t)s3.x * 32 + lane);
        ull v4 = __ldg(base + (size_t)s4.x * 32 + lane);
        ull v5 = __ldg(base + (size_t)s5.x * 32 + lane);
        ull v6 = __ldg(base + (size_t)s6.x * 32 + lane);
        ull v7 = __ldg(base + (size_t)s7.x * 32 + lane);
        a0 = fma2(pack2(__int_as_float(s0.y), __int_as_float(s0.y)), v0, a0);
        a1 = fma2(pack2(__int_as_float(s1.y), __int_as_float(s1.y)), v1, a1);
        a2 = fma2(pack2(__int_as_float(s2.y), __int_as_float(s2.y)), v2, a2);
        a3 = fma2(pack2(__int_as_float(s3.y), __int_as_float(s3.y)), v3, a3);
        a0 = fma2(pack2(__int_as_float(s4.y), __int_as_float(s4.y)), v4, a0);
        a1 = fma2(pack2(__int_as_float(s5.y), __int_as_float(s5.y)), v5, a1);
        a2 = fma2(pack2(__int_as_float(s6.y), __int_as_float(s6.y)), v6, a2);
        a3 = fma2(pack2(__int_as_float(s7.y), __int_as_float(s7.y)), v7, a3);
    }
    for (; e < cnt; e++) {
        int2 sn = __ldg(&row[e]);
        ull v = __ldg(base + (size_t)sn.x * 32 + lane);
        float w = __int_as_float(sn.y);
        a0 = fma2(pack2(w, w), v, a0);
    }

    float2 p = unpack2(add2(add2(a0, a1), add2(a2, a3)));
    ((float2*)(out + (size_t)wg * F_DIM))[lane] = p;
}

// -------- GEMM: [M x 64] * [64 x 64] + bias (+relu), FFMA2-packed.
// 128 rows/block, 8x8 register tile per thread (4 f32x2 pairs wide). --------
__global__ void __launch_bounds__(128) k_gemm(const float* __restrict__ A,
                                              const float* __restrict__ W,
                                              const float* __restrict__ bias,
                                              float* __restrict__ Out,
                                              int do_relu) {
    __shared__ float xs[128][F_DIM];   // 32 KB
    __shared__ float ws[F_DIM][F_DIM]; // 16 KB
    const int tid  = threadIdx.x;
    const size_t row0 = (size_t)blockIdx.x * 128;

    for (int i = tid; i < F_DIM * F_DIM / 4; i += 128)
        ((float4*)ws)[i] = ((const float4*)W)[i];
    {
        const float4* Ag  = (const float4*)(A + row0 * F_DIM);
        float4*       xs4 = (float4*)xs;
        #pragma unroll
        for (int i = 0; i < 16; i++)
            xs4[tid + i * 128] = Ag[tid + i * 128];
    }
    __syncthreads();

    const int tx = tid & 7, ty = tid >> 3;
    const int r0 = ty * 8, c0 = tx * 8;

    ull acc[8][4];
    #pragma unroll
    for (int i = 0; i < 8; i++)
        #pragma unroll
        for (int j = 0; j < 4; j++) acc[i][j] = 0ull;

    #pragma unroll
    for (int k4 = 0; k4 < F_DIM / 4; k4++) {
        float4 a4[8];
        #pragma unroll
        for (int i = 0; i < 8; i++)
            a4[i] = *(const float4*)&xs[r0 + i][k4 * 4];
        #pragma unroll
        for (int kk = 0; kk < 4; kk++) {
            const int k = k4 * 4 + kk;
            const ull* wr = (const ull*)&ws[k][c0];
            ull b0 = wr[0], b1 = wr[1], b2 = wr[2], b3 = wr[3];
            #pragma unroll
            for (int i = 0; i < 8; i++) {
                float a = (kk == 0) ? a4[i].x : (kk == 1) ? a4[i].y
                        : (kk == 2) ? a4[i].z : a4[i].w;
                ull pa = pack2(a, a);
                acc[i][0] = fma2(pa, b0, acc[i][0]);
                acc[i][1] = fma2(pa, b1, acc[i][1]);
                acc[i][2] = fma2(pa, b2, acc[i][2]);
                acc[i][3] = fma2(pa, b3, acc[i][3]);
            }
        }
    }

    ull bb[4];
    #pragma unroll
    for (int jp = 0; jp < 4; jp++)
        bb[jp] = *((const ull*)(bias + c0) + jp);

    #pragma unroll
    for (int i = 0; i < 8; i++) {
        float o[8];
        #pragma unroll
        for (int jp = 0; jp < 4; jp++) {
            float2 v = unpack2(add2(acc[i][jp], bb[jp]));
            o[jp * 2]     = do_relu ? fmaxf(v.x, 0.f) : v.x;
            o[jp * 2 + 1] = do_relu ? fmaxf(v.y, 0.f) : v.y;
        }
        float4* p = (float4*)(Out + (row0 + r0 + i) * F_DIM + c0);
        p[0] = make_float4(o[0], o[1], o[2], o[3]);
        p[1] = make_float4(o[4], o[5], o[6], o[7]);
    }
}

// -------- launch: k_agg is launch index 3 (ncu capture slot) --------
extern "C" void kernel_launch(void* const* d_in, const int* in_sizes, int n_in,
                              void* d_out, int out_size) {
    const float* x   = (const float*)d_in[0];
    const void*  ei  = d_in[1];
    const float* ew  = (const float*)d_in[2];
    const float* W1  = (const float*)d_in[3];
    const float* b1  = (const float*)d_in[4];
    const float* W2  = (const float*)d_in[5];
    const float* b2  = (const float*)d_in[6];
    float*       out = (float*)d_out;

    float *bufA = nullptr, *bufB = nullptr;
    cudaGetSymbolAddress((void**)&bufA, g_bufA);
    cudaGetSymbolAddress((void**)&bufB, g_bufB);

    k_detect_init<<<(E_EDGES + 255) / 256, 256>>>(ei);       // 0
    k_hist       <<<(E_EDGES + 255) / 256, 256>>>(ei, ew);   // 1
    k_fill       <<<(E_EDGES + 255) / 256, 256>>>(ei, ew);   // 2

    // layer 1: out1 = relu((A x) W1 + b1)
    k_agg <<<TN / 8, 256>>>(x, bufA);                        // 3  (ncu target)
    k_gemm<<<TN / 128, 128>>>(bufA, W1, b1, bufB, 1);        // 4
    // layer 2: out = (A out1) W2 + b2
    k_agg <<<TN / 8, 256>>>(bufB, bufA);                     // 5
    k_gemm<<<TN / 128, 128>>>(bufA, W2, b2, out, 0);         // 6
}

// round 5
// speedup vs baseline: 1.2024x; 1.2024x over previous
#include <cuda_runtime.h>

#define T_DIM   32
#define N_NODES 10000
#define E_EDGES 160000
#define F_DIM   64
#define TN      (T_DIM * N_NODES)
#define CAP     64                      // max in-degree bucket capacity

typedef unsigned long long ull;

// ---- packed f32x2 helpers (FFMA2 is PTX-only; ptxas never auto-fuses) ----
__device__ __forceinline__ ull pack2(float lo, float hi) {
    ull r; asm("mov.b64 %0, {%1, %2};" : "=l"(r) : "f"(lo), "f"(hi)); return r;
}
__device__ __forceinline__ float2 unpack2(ull v) {
    float2 r; asm("mov.b64 {%0, %1}, %2;" : "=f"(r.x), "=f"(r.y) : "l"(v)); return r;
}
__device__ __forceinline__ ull fma2(ull a, ull b, ull c) {
    ull d; asm("fma.rn.f32x2 %0, %1, %2, %3;" : "=l"(d) : "l"(a), "l"(b), "l"(c)); return d;
}
__device__ __forceinline__ ull add2(ull a, ull b) {
    ull d; asm("add.rn.f32x2 %0, %1, %2;" : "=l"(d) : "l"(a), "l"(b)); return d;
}

// -------- device scratch (allocation-free rule: __device__ globals) --------
__device__ int   g_i64flag = 1;   // int64-detect: only ever written to 0
__device__ float g_deg[N_NODES];
__device__ int   g_count[N_NODES];
__device__ int2  g_csr[N_NODES * CAP];               // {src, norm_as_int}, 5.1 MB
__device__ float g_bufA[(size_t)TN * F_DIM];         // 81.92 MB
__device__ float g_bufB[(size_t)TN * F_DIM];         // 81.92 MB

__device__ __forceinline__ int edge_src(const void* ei, int e) {
    return g_i64flag ? (int)((const long long*)ei)[e] : ((const int*)ei)[e];
}
__device__ __forceinline__ int edge_dst(const void* ei, int e) {
    return g_i64flag ? (int)((const long long*)ei)[E_EDGES + e]
                     : ((const int*)ei)[E_EDGES + e];
}

// -------- launch 0: dtype detect + zero deg/count --------
__global__ void k_detect_init(const void* __restrict__ ei) {
    int e = blockIdx.x * blockDim.x + threadIdx.x;
    if (e < N_NODES) { g_deg[e] = 0.f; g_count[e] = 0; }
    if (e < E_EDGES) {
        long long v = ((const long long*)ei)[e];   // in-bounds for either dtype
        if (v < 0 || v >= N_NODES) g_i64flag = 0;
    }
}

// -------- launch 1: weighted in-degree --------
__global__ void k_hist(const void* __restrict__ ei, const float* __restrict__ ew) {
    int e = blockIdx.x * blockDim.x + threadIdx.x;
    if (e < E_EDGES) atomicAdd(&g_deg[edge_dst(ei, e)], ew[e]);
}

// -------- launch 2: fill per-dst buckets, dinv inline --------
__global__ void k_fill(const void* __restrict__ ei, const float* __restrict__ ew) {
    int e = blockIdx.x * blockDim.x + threadIdx.x;
    if (e < E_EDGES) {
        int src = edge_src(ei, e);
        int dst = edge_dst(ei, e);
        float ds = g_deg[src], dd = g_deg[dst];
        float is = (ds > 0.f) ? rsqrtf(ds) : 0.f;
        float id = (dd > 0.f) ? rsqrtf(dd) : 0.f;
        float nm = is * ew[e] * id;
        int pos = atomicAdd(&g_count[dst], 1);
        if (pos < CAP)
            g_csr[dst * CAP + pos] = make_int2(src, __float_as_int(nm));
    }
}

// -------- aggregation: block = (node, 8 t-values). Edge list loaded ONCE
// into smem (shared by 8 warps); inner loop = LDS broadcast + gather LDG.
// Block order tg-major: resident wave gathers within one t-slice group. --------
__global__ void __launch_bounds__(256) k_agg(const float* __restrict__ in,
                                             float* __restrict__ out) {
    __shared__ int2 se[CAP];
    const int bid  = blockIdx.x;
    const int tg   = bid / N_NODES;            // 0..3
    const int node = bid - tg * N_NODES;
    const int tid  = threadIdx.x;

    int cnt = g_count[node];
    if (cnt > CAP) cnt = CAP;
    if (tid < cnt) se[tid] = g_csr[node * CAP + tid];
    __syncthreads();

    const int w    = tid >> 5;
    const int lane = tid & 31;
    const int t    = tg * 8 + w;

    // 32-bit offsets: whole buffer < 4GB
    const ull* base = (const ull*)in + (size_t)t * (N_NODES * 32) + lane;

    ull a0 = 0ull, a1 = 0ull, a2 = 0ull, a3 = 0ull;
    int e = 0;
    for (; e + 3 < cnt; e += 4) {
        int2 s0 = se[e];     int2 s1 = se[e + 1];
        int2 s2 = se[e + 2]; int2 s3 = se[e + 3];
        ull v0 = __ldg(base + (unsigned)s0.x * 32u);
        ull v1 = __ldg(base + (unsigned)s1.x * 32u);
        ull v2 = __ldg(base + (unsigned)s2.x * 32u);
        ull v3 = __ldg(base + (unsigned)s3.x * 32u);
        float w0 = __int_as_float(s0.y), w1 = __int_as_float(s1.y);
        float w2 = __int_as_float(s2.y), w3 = __int_as_float(s3.y);
        a0 = fma2(pack2(w0, w0), v0, a0);
        a1 = fma2(pack2(w1, w1), v1, a1);
        a2 = fma2(pack2(w2, w2), v2, a2);
        a3 = fma2(pack2(w3, w3), v3, a3);
    }
    for (; e < cnt; e++) {
        int2 sn = se[e];
        ull v = __ldg(base + (unsigned)sn.x * 32u);
        float ww = __int_as_float(sn.y);
        a0 = fma2(pack2(ww, ww), v, a0);
    }

    float2 p = unpack2(add2(add2(a0, a1), add2(a2, a3)));
    ((float2*)out)[(size_t)(t * N_NODES + node) * 32 + lane] = p;
}

// -------- GEMM: [M x 64] * [64 x 64] + bias (+relu), FFMA2-packed. --------
__global__ void __launch_bounds__(128) k_gemm(const float* __restrict__ A,
                                              const float* __restrict__ W,
                                              const float* __restrict__ bias,
                                              float* __restrict__ Out,
                                              int do_relu) {
    __shared__ float xs[128][F_DIM];   // 32 KB
    __shared__ float ws[F_DIM][F_DIM]; // 16 KB
    const int tid  = threadIdx.x;
    const size_t row0 = (size_t)blockIdx.x * 128;

    for (int i = tid; i < F_DIM * F_DIM / 4; i += 128)
        ((float4*)ws)[i] = ((const float4*)W)[i];
    {
        const float4* Ag  = (const float4*)(A + row0 * F_DIM);
        float4*       xs4 = (float4*)xs;
        #pragma unroll
        for (int i = 0; i < 16; i++)
            xs4[tid + i * 128] = Ag[tid + i * 128];
    }
    __syncthreads();

    const int tx = tid & 7, ty = tid >> 3;
    const int r0 = ty * 8, c0 = tx * 8;

    ull acc[8][4];
    #pragma unroll
    for (int i = 0; i < 8; i++)
        #pragma unroll
        for (int j = 0; j < 4; j++) acc[i][j] = 0ull;

    #pragma unroll
    for (int k4 = 0; k4 < F_DIM / 4; k4++) {
        float4 a4[8];
        #pragma unroll
        for (int i = 0; i < 8; i++)
            a4[i] = *(const float4*)&xs[r0 + i][k4 * 4];
        #pragma unroll
        for (int kk = 0; kk < 4; kk++) {
            const int k = k4 * 4 + kk;
            const ull* wr = (const ull*)&ws[k][c0];
            ull b0 = wr[0], b1 = wr[1], b2 = wr[2], b3 = wr[3];
            #pragma unroll
            for (int i = 0; i < 8; i++) {
                float a = (kk == 0) ? a4[i].x : (kk == 1) ? a4[i].y
                        : (kk == 2) ? a4[i].z : a4[i].w;
                ull pa = pack2(a, a);
                acc[i][0] = fma2(pa, b0, acc[i][0]);
                acc[i][1] = fma2(pa, b1, acc[i][1]);
                acc[i][2] = fma2(pa, b2, acc[i][2]);
                acc[i][3] = fma2(pa, b3, acc[i][3]);
            }
        }
    }

    ull bb[4];
    #pragma unroll
    for (int jp = 0; jp < 4; jp++)
        bb[jp] = *((const ull*)(bias + c0) + jp);

    #pragma unroll
    for (int i = 0; i < 8; i++) {
        float o[8];
        #pragma unroll
        for (int jp = 0; jp < 4; jp++) {
            float2 v = unpack2(add2(acc[i][jp], bb[jp]));
            o[jp * 2]     = do_relu ? fmaxf(v.x, 0.f) : v.x;
            o[jp * 2 + 1] = do_relu ? fmaxf(v.y, 0.f) : v.y;
        }
        float4* p = (float4*)(Out + (row0 + r0 + i) * F_DIM + c0);
        p[0] = make_float4(o[0], o[1], o[2], o[3]);
        p[1] = make_float4(o[4], o[5], o[6], o[7]);
    }
}

// -------- launch: k_agg is launch index 3 (ncu capture slot) --------
extern "C" void kernel_launch(void* const* d_in, const int* in_sizes, int n_in,
                              void* d_out, int out_size) {
    const float* x   = (const float*)d_in[0];
    const void*  ei  = d_in[1];
    const float* ew  = (const float*)d_in[2];
    const float* W1  = (const float*)d_in[3];
    const float* b1  = (const float*)d_in[4];
    const float* W2  = (const float*)d_in[5];
    const float* b2  = (const float*)d_in[6];
    float*       out = (float*)d_out;

    float *bufA = nullptr, *bufB = nullptr;
    cudaGetSymbolAddress((void**)&bufA, g_bufA);
    cudaGetSymbolAddress((void**)&bufB, g_bufB);

    k_detect_init<<<(E_EDGES + 255) / 256, 256>>>(ei);       // 0
    k_hist       <<<(E_EDGES + 255) / 256, 256>>>(ei, ew);   // 1
    k_fill       <<<(E_EDGES + 255) / 256, 256>>>(ei, ew);   // 2

    // layer 1: out1 = relu((A x) W1 + b1)
    k_agg <<<N_NODES * (T_DIM / 8), 256>>>(x, bufA);         // 3  (ncu target)
    k_gemm<<<TN / 128, 128>>>(bufA, W1, b1, bufB, 1);        // 4
    // layer 2: out = (A out1) W2 + b2
    k_agg <<<N_NODES * (T_DIM / 8), 256>>>(bufB, bufA);      // 5
    k_gemm<<<TN / 128, 128>>>(bufA, W2, b2, out, 0);         // 6
}

// round 6
// speedup vs baseline: 1.2104x; 1.0066x over previous
#include <cuda_runtime.h>

#define T_DIM   32
#define N_NODES 10000
#define E_EDGES 160000
#define F_DIM   64
#define TN      (T_DIM * N_NODES)
#define CAP     64                      // max in-degree bucket capacity

typedef unsigned long long ull;

// ---- packed f32x2 helpers (FFMA2 is PTX-only; ptxas never auto-fuses) ----
__device__ __forceinline__ ull pack2(float lo, float hi) {
    ull r; asm("mov.b64 %0, {%1, %2};" : "=l"(r) : "f"(lo), "f"(hi)); return r;
}
__device__ __forceinline__ float2 unpack2(ull v) {
    float2 r; asm("mov.b64 {%0, %1}, %2;" : "=f"(r.x), "=f"(r.y) : "l"(v)); return r;
}
__device__ __forceinline__ ull fma2(ull a, ull b, ull c) {
    ull d; asm("fma.rn.f32x2 %0, %1, %2, %3;" : "=l"(d) : "l"(a), "l"(b), "l"(c)); return d;
}
__device__ __forceinline__ ull add2(ull a, ull b) {
    ull d; asm("add.rn.f32x2 %0, %1, %2;" : "=l"(d) : "l"(a), "l"(b)); return d;
}

// -------- device scratch (allocation-free rule: __device__ globals) --------
__device__ int   g_i64flag = 1;   // int64-detect: only ever written to 0
__device__ float g_deg[N_NODES];
__device__ int   g_count[N_NODES];
__device__ int2  g_csr[N_NODES * CAP];               // {src, norm_as_int}, 5.1 MB
__device__ float g_bufA[(size_t)TN * F_DIM];         // 81.92 MB
__device__ float g_bufB[(size_t)TN * F_DIM];         // 81.92 MB

__device__ __forceinline__ int edge_src(const void* ei, int e) {
    return g_i64flag ? (int)((const long long*)ei)[e] : ((const int*)ei)[e];
}
__device__ __forceinline__ int edge_dst(const void* ei, int e) {
    return g_i64flag ? (int)((const long long*)ei)[E_EDGES + e]
                     : ((const int*)ei)[E_EDGES + e];
}

// -------- launch 0: dtype detect + zero deg/count --------
__global__ void k_detect_init(const void* __restrict__ ei) {
    int e = blockIdx.x * blockDim.x + threadIdx.x;
    if (e < N_NODES) { g_deg[e] = 0.f; g_count[e] = 0; }
    if (e < E_EDGES) {
        long long v = ((const long long*)ei)[e];   // in-bounds for either dtype
        if (v < 0 || v >= N_NODES) g_i64flag = 0;
    }
}

// -------- launch 1: weighted in-degree --------
__global__ void k_hist(const void* __restrict__ ei, const float* __restrict__ ew) {
    int e = blockIdx.x * blockDim.x + threadIdx.x;
    if (e < E_EDGES) atomicAdd(&g_deg[edge_dst(ei, e)], ew[e]);
}

// -------- launch 2: fill per-dst buckets, dinv inline --------
__global__ void k_fill(const void* __restrict__ ei, const float* __restrict__ ew) {
    int e = blockIdx.x * blockDim.x + threadIdx.x;
    if (e < E_EDGES) {
        int src = edge_src(ei, e);
        int dst = edge_dst(ei, e);
        float ds = g_deg[src], dd = g_deg[dst];
        float is = (ds > 0.f) ? rsqrtf(ds) : 0.f;
        float id = (dd > 0.f) ? rsqrtf(dd) : 0.f;
        float nm = is * ew[e] * id;
        int pos = atomicAdd(&g_count[dst], 1);
        if (pos < CAP)
            g_csr[dst * CAP + pos] = make_int2(src, __float_as_int(nm));
    }
}

// -------- aggregation: block = (node, 8 t-values); edge list in smem.
// Split-lane gathers: lanes 0-15 do edge e, lanes 16-31 edge e+1, each
// lane fetching a float4 (LDG.128) -> one instruction covers TWO edges. --------
__global__ void __launch_bounds__(256) k_agg(const float* __restrict__ in,
                                             float* __restrict__ out) {
    __shared__ int2 se[CAP];
    const int bid  = blockIdx.x;
    const int tg   = bid / N_NODES;            // 0..3
    const int node = bid - tg * N_NODES;
    const int tid  = threadIdx.x;

    int cnt = g_count[node];
    if (cnt > CAP) cnt = CAP;
    if (tid < cnt) se[tid] = g_csr[node * CAP + tid];
    __syncthreads();

    const int w    = tid >> 5;
    const int lane = tid & 31;
    const int half = lane >> 4;                // 0: edge e, 1: edge e+1
    const int hl   = lane & 15;                // float4 slot within row
    const int t    = tg * 8 + w;

    // 32-bit offsets: whole buffer < 4 GB. Row = 16 float4s.
    const float4* base = (const float4*)in + (size_t)t * (N_NODES * 16) + hl;

    ull a0 = 0ull, a1 = 0ull, a2 = 0ull, a3 = 0ull;
    int e = 0;
    for (; e + 7 < cnt; e += 8) {
        int2 s0 = se[e     + half];
        int2 s1 = se[e + 2 + half];
        int2 s2 = se[e + 4 + half];
        int2 s3 = se[e + 6 + half];
        float4 v0 = __ldg(base + (unsigned)s0.x * 16u);
        float4 v1 = __ldg(base + (unsigned)s1.x * 16u);
        float4 v2 = __ldg(base + (unsigned)s2.x * 16u);
        float4 v3 = __ldg(base + (unsigned)s3.x * 16u);
        float w0 = __int_as_float(s0.y), w1 = __int_as_float(s1.y);
        float w2 = __int_as_float(s2.y), w3 = __int_as_float(s3.y);
        a0 = fma2(pack2(w0, w0), pack2(v0.x, v0.y), a0);
        a1 = fma2(pack2(w0, w0), pack2(v0.z, v0.w), a1);
        a2 = fma2(pack2(w1, w1), pack2(v1.x, v1.y), a2);
        a3 = fma2(pack2(w1, w1), pack2(v1.z, v1.w), a3);
        a0 = fma2(pack2(w2, w2), pack2(v2.x, v2.y), a0);
        a1 = fma2(pack2(w2, w2), pack2(v2.z, v2.w), a1);
        a2 = fma2(pack2(w3, w3), pack2(v3.x, v3.y), a2);
        a3 = fma2(pack2(w3, w3), pack2(v3.z, v3.w), a3);
    }
    for (; e < cnt; e += 2) {
        int idx = e + half;
        if (idx < cnt) {
            int2 sn = se[idx];
            float4 v = __ldg(base + (unsigned)sn.x * 16u);
            float ww = __int_as_float(sn.y);
            a0 = fma2(pack2(ww, ww), pack2(v.x, v.y), a0);
            a1 = fma2(pack2(ww, ww), pack2(v.z, v.w), a1);
        }
    }

    a0 = add2(a0, a2);
    a1 = add2(a1, a3);
    // combine the two halves (high-lane partials onto low lanes)
    ull b0 = __shfl_down_sync(0xffffffffu, a0, 16);
    ull b1 = __shfl_down_sync(0xffffffffu, a1, 16);
    if (half == 0) {
        a0 = add2(a0, b0);
        a1 = add2(a1, b1);
        float2 p0 = unpack2(a0), p1 = unpack2(a1);
        float4* op = (float4*)out + (size_t)(t * N_NODES + node) * 16 + hl;
        *op = make_float4(p0.x, p0.y, p1.x, p1.y);
    }
}

// -------- GEMM: [M x 64] * [64 x 64] + bias (+relu), FFMA2-packed. --------
__global__ void __launch_bounds__(128) k_gemm(const float* __restrict__ A,
                                              const float* __restrict__ W,
                                              const float* __restrict__ bias,
                                              float* __restrict__ Out,
                                              int do_relu) {
    __shared__ float xs[128][F_DIM];   // 32 KB
    __shared__ float ws[F_DIM][F_DIM]; // 16 KB
    const int tid  = threadIdx.x;
    const size_t row0 = (size_t)blockIdx.x * 128;

    for (int i = tid; i < F_DIM * F_DIM / 4; i += 128)
        ((float4*)ws)[i] = ((const float4*)W)[i];
    {
        const float4* Ag  = (const float4*)(A + row0 * F_DIM);
        float4*       xs4 = (float4*)xs;
        #pragma unroll
        for (int i = 0; i < 16; i++)
            xs4[tid + i * 128] = Ag[tid + i * 128];
    }
    __syncthreads();

    const int tx = tid & 7, ty = tid >> 3;
    const int r0 = ty * 8, c0 = tx * 8;

    ull acc[8][4];
    #pragma unroll
    for (int i = 0; i < 8; i++)
        #pragma unroll
        for (int j = 0; j < 4; j++) acc[i][j] = 0ull;

    #pragma unroll
    for (int k4 = 0; k4 < F_DIM / 4; k4++) {
        float4 a4[8];
        #pragma unroll
        for (int i = 0; i < 8; i++)
            a4[i] = *(const float4*)&xs[r0 + i][k4 * 4];
        #pragma unroll
        for (int kk = 0; kk < 4; kk++) {
            const int k = k4 * 4 + kk;
            ulonglong2 bl = *(const ulonglong2*)&ws[k][c0];       // LDS.128
            ulonglong2 bh = *(const ulonglong2*)&ws[k][c0 + 4];   // LDS.128
            #pragma unroll
            for (int i = 0; i < 8; i++) {
                float a = (kk == 0) ? a4[i].x : (kk == 1) ? a4[i].y
                        : (kk == 2) ? a4[i].z : a4[i].w;
                ull pa = pack2(a, a);
                acc[i][0] = fma2(pa, bl.x, acc[i][0]);
                acc[i][1] = fma2(pa, bl.y, acc[i][1]);
                acc[i][2] = fma2(pa, bh.x, acc[i][2]);
                acc[i][3] = fma2(pa, bh.y, acc[i][3]);
            }
        }
    }

    ull bb[4];
    #pragma unroll
    for (int jp = 0; jp < 4; jp++)
        bb[jp] = *((const ull*)(bias + c0) + jp);

    #pragma unroll
    for (int i = 0; i < 8; i++) {
        float o[8];
        #pragma unroll
        for (int jp = 0; jp < 4; jp++) {
            float2 v = unpack2(add2(acc[i][jp], bb[jp]));
            o[jp * 2]     = do_relu ? fmaxf(v.x, 0.f) : v.x;
            o[jp * 2 + 1] = do_relu ? fmaxf(v.y, 0.f) : v.y;
        }
        float4* p = (float4*)(Out + (row0 + r0 + i) * F_DIM + c0);
        p[0] = make_float4(o[0], o[1], o[2], o[3]);
        p[1] = make_float4(o[4], o[5], o[6], o[7]);
    }
}

// -------- launch: k_agg is launch index 3 (ncu capture slot) --------
extern "C" void kernel_launch(void* const* d_in, const int* in_sizes, int n_in,
                              void* d_out, int out_size) {
    const float* x   = (const float*)d_in[0];
    const void*  ei  = d_in[1];
    const float* ew  = (const float*)d_in[2];
    const float* W1  = (const float*)d_in[3];
    const float* b1  = (const float*)d_in[4];
    const float* W2  = (const float*)d_in[5];
    const float* b2  = (const float*)d_in[6];
    float*       out = (float*)d_out;

    float *bufA = nullptr, *bufB = nullptr;
    cudaGetSymbolAddress((void**)&bufA, g_bufA);
    cudaGetSymbolAddress((void**)&bufB, g_bufB);

    k_detect_init<<<(E_EDGES + 255) / 256, 256>>>(ei);       // 0
    k_hist       <<<(E_EDGES + 255) / 256, 256>>>(ei, ew);   // 1
    k_fill       <<<(E_EDGES + 255) / 256, 256>>>(ei, ew);   // 2

    // layer 1: out1 = relu((A x) W1 + b1)
    k_agg <<<N_NODES * (T_DIM / 8), 256>>>(x, bufA);         // 3  (ncu target)
    k_gemm<<<TN / 128, 128>>>(bufA, W1, b1, bufB, 1);        // 4
    // layer 2: out = (A out1) W2 + b2
    k_agg <<<N_NODES * (T_DIM / 8), 256>>>(bufB, bufA);      // 5
    k_gemm<<<TN / 128, 128>>>(bufA, W2, b2, out, 0);         // 6
}

// round 7
// speedup vs baseline: 1.2363x; 1.0214x over previous
#include <cuda_runtime.h>

#define T_DIM   32
#define N_NODES 10000
#define E_EDGES 160000
#define F_DIM   64
#define TN      (T_DIM * N_NODES)
#define CAP     64                      // max in-degree bucket capacity

typedef unsigned long long ull;

// ---- packed f32x2 helpers (FFMA2 is PTX-only; ptxas never auto-fuses) ----
__device__ __forceinline__ ull pack2(float lo, float hi) {
    ull r; asm("mov.b64 %0, {%1, %2};" : "=l"(r) : "f"(lo), "f"(hi)); return r;
}
__device__ __forceinline__ float2 unpack2(ull v) {
    float2 r; asm("mov.b64 {%0, %1}, %2;" : "=f"(r.x), "=f"(r.y) : "l"(v)); return r;
}
__device__ __forceinline__ ull fma2(ull a, ull b, ull c) {
    ull d; asm("fma.rn.f32x2 %0, %1, %2, %3;" : "=l"(d) : "l"(a), "l"(b), "l"(c)); return d;
}
__device__ __forceinline__ ull add2(ull a, ull b) {
    ull d; asm("add.rn.f32x2 %0, %1, %2;" : "=l"(d) : "l"(a), "l"(b)); return d;
}
__device__ __forceinline__ float hsum2(ull v) {
    float2 p = unpack2(v); return p.x + p.y;
}

// -------- device scratch (allocation-free rule: __device__ globals) --------
__device__ int   g_i64flag = 1;   // int64-detect: only ever written to 0
__device__ float g_deg[N_NODES];
__device__ int   g_count[N_NODES];
__device__ int2  g_csr[N_NODES * CAP];               // {src, norm_as_int}, 5.1 MB
__device__ float g_bufA[(size_t)TN * F_DIM];         // 81.92 MB
__device__ float g_bufB[(size_t)TN * F_DIM];         // 81.92 MB

__device__ __forceinline__ int edge_src(const void* ei, int e) {
    return g_i64flag ? (int)((const long long*)ei)[e] : ((const int*)ei)[e];
}
__device__ __forceinline__ int edge_dst(const void* ei, int e) {
    return g_i64flag ? (int)((const long long*)ei)[E_EDGES + e]
                     : ((const int*)ei)[E_EDGES + e];
}

// -------- launch 0: dtype detect + zero deg/count --------
__global__ void k_detect_init(const void* __restrict__ ei) {
    int e = blockIdx.x * blockDim.x + threadIdx.x;
    if (e < N_NODES) { g_deg[e] = 0.f; g_count[e] = 0; }
    if (e < E_EDGES) {
        long long v = ((const long long*)ei)[e];   // in-bounds for either dtype
        if (v < 0 || v >= N_NODES) g_i64flag = 0;
    }
}

// -------- launch 1: weighted in-degree --------
__global__ void k_hist(const void* __restrict__ ei, const float* __restrict__ ew) {
    int e = blockIdx.x * blockDim.x + threadIdx.x;
    if (e < E_EDGES) atomicAdd(&g_deg[edge_dst(ei, e)], ew[e]);
}

// -------- launch 2: fill per-dst buckets, dinv inline --------
__global__ void k_fill(const void* __restrict__ ei, const float* __restrict__ ew) {
    int e = blockIdx.x * blockDim.x + threadIdx.x;
    if (e < E_EDGES) {
        int src = edge_src(ei, e);
        int dst = edge_dst(ei, e);
        float ds = g_deg[src], dd = g_deg[dst];
        float is = (ds > 0.f) ? rsqrtf(ds) : 0.f;
        float id = (dd > 0.f) ? rsqrtf(dd) : 0.f;
        float nm = is * ew[e] * id;
        int pos = atomicAdd(&g_count[dst], 1);
        if (pos < CAP)
            g_csr[dst * CAP + pos] = make_int2(src, __float_as_int(nm));
    }
}

// -------- GEMM (no bias/relu): C = A[Mx64] * W[64x64], k-packed FFMA2.
// acc halves hold even-k / odd-k partial sums; A k-pairs are free 64-bit
// smem reads; W stored k-pair interleaved -> zero packing MOVs. --------
__global__ void __launch_bounds__(256) k_gemm(const float* __restrict__ A,
                                              const float* __restrict__ W,
                                              float* __restrict__ Out) {
    __shared__ float xs[128 * F_DIM];    // 32 KB  A tile
    __shared__ float wsp[32 * 128];      // 16 KB  wsp[kp][2c+h] = W[2kp+h][c]
    const int tid  = threadIdx.x;
    const size_t row0 = (size_t)blockIdx.x * 128;

    // W: 1024 float4 reads, scatter into k-pair-interleaved layout
    for (int i = tid; i < 1024; i += 256) {
        float4 w4 = ((const float4*)W)[i];
        int k = (i * 4) >> 6;            // source row (k)
        int c = (i * 4) & 63;            // source col base
        float* dr = &wsp[(k >> 1) * 128 + (k & 1)];
        dr[2 * c]       = w4.x;
        dr[2 * (c + 1)] = w4.y;
        dr[2 * (c + 2)] = w4.z;
        dr[2 * (c + 3)] = w4.w;
    }
    {
        const float4* Ag  = (const float4*)(A + row0 * F_DIM);
        float4*       xs4 = (float4*)xs;
        #pragma unroll
        for (int i = 0; i < 8; i++)
            xs4[tid + i * 256] = Ag[tid + i * 256];
    }
    __syncthreads();

    const int tx = tid & 15, ty = tid >> 4;
    const int r0 = ty * 8, c0 = tx * 4;

    ull acc[8][4];
    #pragma unroll
    for (int i = 0; i < 8; i++)
        #pragma unroll
        for (int j = 0; j < 4; j++) acc[i][j] = 0ull;

    #pragma unroll
    for (int kk2 = 0; kk2 < 16; kk2++) {          // 2 k-pairs (4 k) per iter
        const ull* w0 = (const ull*)wsp + (2 * kk2) * 64 + c0;   // kpair 2kk2
        const ull* w1 = w0 + 64;                                  // kpair 2kk2+1
        ulonglong2 wa0 = *(const ulonglong2*)w0;
        ulonglong2 wa1 = *(const ulonglong2*)(w0 + 2);
        ulonglong2 wb0 = *(const ulonglong2*)w1;
        ulonglong2 wb1 = *(const ulonglong2*)(w1 + 2);
        #pragma unroll
        for (int i = 0; i < 8; i++) {
            ulonglong2 av = *(const ulonglong2*)&xs[(r0 + i) * F_DIM + kk2 * 4];
            acc[i][0] = fma2(av.x, wa0.x, acc[i][0]);
            acc[i][1] = fma2(av.x, wa0.y, acc[i][1]);
            acc[i][2] = fma2(av.x, wa1.x, acc[i][2]);
            acc[i][3] = fma2(av.x, wa1.y, acc[i][3]);
            acc[i][0] = fma2(av.y, wb0.x, acc[i][0]);
            acc[i][1] = fma2(av.y, wb0.y, acc[i][1]);
            acc[i][2] = fma2(av.y, wb1.x, acc[i][2]);
            acc[i][3] = fma2(av.y, wb1.y, acc[i][3]);
        }
    }

    #pragma unroll
    for (int i = 0; i < 8; i++) {
        float4 o = make_float4(hsum2(acc[i][0]), hsum2(acc[i][1]),
                               hsum2(acc[i][2]), hsum2(acc[i][3]));
        *(float4*)(Out + (row0 + r0 + i) * F_DIM + c0) = o;
    }
}

// -------- aggregation: block = (node, 8 t-values); edge list in smem.
// Split-lane LDG.128 gathers (2 edges per instruction). Bias (+relu)
// fused in the epilogue (out = A*in + b, optional relu). --------
__global__ void __launch_bounds__(256) k_agg(const float* __restrict__ in,
                                             const float* __restrict__ bias,
                                             float* __restrict__ out,
                                             int do_relu) {
    __shared__ int2 se[CAP];
    const int bid  = blockIdx.x;
    const int tg   = bid / N_NODES;            // 0..3
    const int node = bid - tg * N_NODES;
    const int tid  = threadIdx.x;

    int cnt = g_count[node];
    if (cnt > CAP) cnt = CAP;
    if (tid < cnt) se[tid] = g_csr[node * CAP + tid];
    __syncthreads();

    const int w    = tid >> 5;
    const int lane = tid & 31;
    const int half = lane >> 4;                // 0: edge e, 1: edge e+1
    const int hl   = lane & 15;                // float4 slot within row
    const int t    = tg * 8 + w;

    const float4* base = (const float4*)in + (size_t)t * (N_NODES * 16) + hl;

    ull a0 = 0ull, a1 = 0ull, a2 = 0ull, a3 = 0ull;
    int e = 0;
    for (; e + 7 < cnt; e += 8) {
        int2 s0 = se[e     + half];
        int2 s1 = se[e + 2 + half];
        int2 s2 = se[e + 4 + half];
        int2 s3 = se[e + 6 + half];
        float4 v0 = __ldg(base + (unsigned)s0.x * 16u);
        float4 v1 = __ldg(base + (unsigned)s1.x * 16u);
        float4 v2 = __ldg(base + (unsigned)s2.x * 16u);
        float4 v3 = __ldg(base + (unsigned)s3.x * 16u);
        float w0 = __int_as_float(s0.y), w1 = __int_as_float(s1.y);
        float w2 = __int_as_float(s2.y), w3 = __int_as_float(s3.y);
        a0 = fma2(pack2(w0, w0), pack2(v0.x, v0.y), a0);
        a1 = fma2(pack2(w0, w0), pack2(v0.z, v0.w), a1);
        a2 = fma2(pack2(w1, w1), pack2(v1.x, v1.y), a2);
        a3 = fma2(pack2(w1, w1), pack2(v1.z, v1.w), a3);
        a0 = fma2(pack2(w2, w2), pack2(v2.x, v2.y), a0);
        a1 = fma2(pack2(w2, w2), pack2(v2.z, v2.w), a1);
        a2 = fma2(pack2(w3, w3), pack2(v3.x, v3.y), a2);
        a3 = fma2(pack2(w3, w3), pack2(v3.z, v3.w), a3);
    }
    for (; e < cnt; e += 2) {
        int idx = e + half;
        if (idx < cnt) {
            int2 sn = se[idx];
            float4 v = __ldg(base + (unsigned)sn.x * 16u);
            float ww = __int_as_float(sn.y);
            a0 = fma2(pack2(ww, ww), pack2(v.x, v.y), a0);
            a1 = fma2(pack2(ww, ww), pack2(v.z, v.w), a1);
        }
    }

    a0 = add2(a0, a2);
    a1 = add2(a1, a3);
    ull b0 = __shfl_down_sync(0xffffffffu, a0, 16);
    ull b1 = __shfl_down_sync(0xffffffffu, a1, 16);
    if (half == 0) {
        a0 = add2(a0, b0);
        a1 = add2(a1, b1);
        float2 p0 = unpack2(a0), p1 = unpack2(a1);
        float4 bv = __ldg((const float4*)bias + hl);
        float4 o = make_float4(p0.x + bv.x, p0.y + bv.y,
                               p1.x + bv.z, p1.y + bv.w);
        if (do_relu) {
            o.x = fmaxf(o.x, 0.f); o.y = fmaxf(o.y, 0.f);
            o.z = fmaxf(o.z, 0.f); o.w = fmaxf(o.w, 0.f);
        }
        float4* op = (float4*)out + (size_t)(t * N_NODES + node) * 16 + hl;
        *op = o;
    }
}

// -------- launch: (A X) W == A (X W)  ->  GEMM first, bias+relu in agg.
// k_gemm lands at launch index 3 (the ncu capture slot). --------
extern "C" void kernel_launch(void* const* d_in, const int* in_sizes, int n_in,
                              void* d_out, int out_size) {
    const float* x   = (const float*)d_in[0];
    const void*  ei  = d_in[1];
    const float* ew  = (const float*)d_in[2];
    const float* W1  = (const float*)d_in[3];
    const float* b1  = (const float*)d_in[4];
    const float* W2  = (const float*)d_in[5];
    const float* b2  = (const float*)d_in[6];
    float*       out = (float*)d_out;

    float *bufA = nullptr, *bufB = nullptr;
    cudaGetSymbolAddress((void**)&bufA, g_bufA);
    cudaGetSymbolAddress((void**)&bufB, g_bufB);

    k_detect_init<<<(E_EDGES + 255) / 256, 256>>>(ei);       // 0
    k_hist       <<<(E_EDGES + 255) / 256, 256>>>(ei, ew);   // 1
    k_fill       <<<(E_EDGES + 255) / 256, 256>>>(ei, ew);   // 2

    // layer 1: h = relu(A (x W1) + b1)
    k_gemm<<<TN / 128, 256>>>(x, W1, bufA);                  // 3  (ncu target)
    k_agg <<<N_NODES * (T_DIM / 8), 256>>>(bufA, b1, bufB, 1);   // 4
    // layer 2: out = A (h W2) + b2
    k_gemm<<<TN / 128, 256>>>(bufB, W2, bufA);               // 5
    k_agg <<<N_NODES * (T_DIM / 8), 256>>>(bufA, b2, out, 0);    // 6
}

// round 8
// speedup vs baseline: 1.4353x; 1.1610x over previous
#include <cuda_runtime.h>
#include <cuda_fp16.h>

#define T_DIM   32
#define N_NODES 10000
#define E_EDGES 160000
#define F_DIM   64
#define TN      (T_DIM * N_NODES)
#define CAP     64                      // max in-degree bucket capacity

typedef unsigned long long ull;

// ---- packed f32x2 helpers (FFMA2 is PTX-only; ptxas never auto-fuses) ----
__device__ __forceinline__ ull pack2(float lo, float hi) {
    ull r; asm("mov.b64 %0, {%1, %2};" : "=l"(r) : "f"(lo), "f"(hi)); return r;
}
__device__ __forceinline__ float2 unpack2(ull v) {
    float2 r; asm("mov.b64 {%0, %1}, %2;" : "=f"(r.x), "=f"(r.y) : "l"(v)); return r;
}
__device__ __forceinline__ ull fma2(ull a, ull b, ull c) {
    ull d; asm("fma.rn.f32x2 %0, %1, %2, %3;" : "=l"(d) : "l"(a), "l"(b), "l"(c)); return d;
}
__device__ __forceinline__ ull add2(ull a, ull b) {
    ull d; asm("add.rn.f32x2 %0, %1, %2;" : "=l"(d) : "l"(a), "l"(b)); return d;
}
__device__ __forceinline__ float hsum2(ull v) {
    float2 p = unpack2(v); return p.x + p.y;
}
// 4 floats -> 4 halves packed in one ull
__device__ __forceinline__ ull f4_to_h4(float a, float b, float c, float d) {
    __half2 lo = __float22half2_rn(make_float2(a, b));
    __half2 hi = __float22half2_rn(make_float2(c, d));
    ull r;
    asm("mov.b64 %0, {%1, %2};" : "=l"(r)
        : "r"(*(unsigned*)&lo), "r"(*(unsigned*)&hi));
    return r;
}

// -------- device scratch (allocation-free rule: __device__ globals) --------
__device__ int    g_i64flag = 1;   // int64-detect: only ever written to 0
__device__ float  g_deg[N_NODES];
__device__ int    g_count[N_NODES];
__device__ int2   g_csr[N_NODES * CAP];               // {src, norm_as_int}
__device__ __half g_h1[(size_t)TN * F_DIM];           // 40.96 MB
__device__ __half g_h2[(size_t)TN * F_DIM];           // 40.96 MB

__device__ __forceinline__ int edge_src(const void* ei, int e) {
    return g_i64flag ? (int)((const long long*)ei)[e] : ((const int*)ei)[e];
}
__device__ __forceinline__ int edge_dst(const void* ei, int e) {
    return g_i64flag ? (int)((const long long*)ei)[E_EDGES + e]
                     : ((const int*)ei)[E_EDGES + e];
}

// -------- launch 0: dtype detect + zero deg/count --------
__global__ void k_detect_init(const void* __restrict__ ei) {
    int e = blockIdx.x * blockDim.x + threadIdx.x;
    if (e < N_NODES) { g_deg[e] = 0.f; g_count[e] = 0; }
    if (e < E_EDGES) {
        long long v = ((const long long*)ei)[e];   // in-bounds for either dtype
        if (v < 0 || v >= N_NODES) g_i64flag = 0;
    }
}

// -------- launch 1: weighted in-degree --------
__global__ void k_hist(const void* __restrict__ ei, const float* __restrict__ ew) {
    int e = blockIdx.x * blockDim.x + threadIdx.x;
    if (e < E_EDGES) atomicAdd(&g_deg[edge_dst(ei, e)], ew[e]);
}

// -------- launch 2: fill per-dst buckets, dinv inline --------
__global__ void k_fill(const void* __restrict__ ei, const float* __restrict__ ew) {
    int e = blockIdx.x * blockDim.x + threadIdx.x;
    if (e < E_EDGES) {
        int src = edge_src(ei, e);
        int dst = edge_dst(ei, e);
        float ds = g_deg[src], dd = g_deg[dst];
        float is = (ds > 0.f) ? rsqrtf(ds) : 0.f;
        float id = (dd > 0.f) ? rsqrtf(dd) : 0.f;
        float nm = is * ew[e] * id;
        int pos = atomicAdd(&g_count[dst], 1);
        if (pos < CAP)
            g_csr[dst * CAP + pos] = make_int2(src, __float_as_int(nm));
    }
}

// -------- GEMM core: C[128x64] = xs * W (k-pair-packed FFMA2), fp16 out --------
__device__ __forceinline__ void gemm_core(const float* xs, const float* wsp,
                                          int tid, size_t row0,
                                          __half* __restrict__ Out) {
    const int tx = tid & 15, ty = tid >> 4;
    const int r0 = ty * 8, c0 = tx * 4;

    ull acc[8][4];
    #pragma unroll
    for (int i = 0; i < 8; i++)
        #pragma unroll
        for (int j = 0; j < 4; j++) acc[i][j] = 0ull;

    #pragma unroll
    for (int kk2 = 0; kk2 < 16; kk2++) {          // 2 k-pairs (4 k) per iter
        const ull* w0 = (const ull*)wsp + (2 * kk2) * 64 + c0;
        const ull* w1 = w0 + 64;
        ulonglong2 wa0 = *(const ulonglong2*)w0;
        ulonglong2 wa1 = *(const ulonglong2*)(w0 + 2);
        ulonglong2 wb0 = *(const ulonglong2*)w1;
        ulonglong2 wb1 = *(const ulonglong2*)(w1 + 2);
        #pragma unroll
        for (int i = 0; i < 8; i++) {
            ulonglong2 av = *(const ulonglong2*)&xs[(r0 + i) * F_DIM + kk2 * 4];
            acc[i][0] = fma2(av.x, wa0.x, acc[i][0]);
            acc[i][1] = fma2(av.x, wa0.y, acc[i][1]);
            acc[i][2] = fma2(av.x, wa1.x, acc[i][2]);
            acc[i][3] = fma2(av.x, wa1.y, acc[i][3]);
            acc[i][0] = fma2(av.y, wb0.x, acc[i][0]);
            acc[i][1] = fma2(av.y, wb0.y, acc[i][1]);
            acc[i][2] = fma2(av.y, wb1.x, acc[i][2]);
            acc[i][3] = fma2(av.y, wb1.y, acc[i][3]);
        }
    }

    #pragma unroll
    for (int i = 0; i < 8; i++) {
        ull h4 = f4_to_h4(hsum2(acc[i][0]), hsum2(acc[i][1]),
                          hsum2(acc[i][2]), hsum2(acc[i][3]));
        ((ull*)(Out + (row0 + r0 + i) * F_DIM))[c0 >> 2] = h4;
    }
}

__device__ __forceinline__ void load_w(const float* __restrict__ W,
                                       float* wsp, int tid) {
    // W: 1024 float4 reads, scatter into k-pair-interleaved layout
    for (int i = tid; i < 1024; i += 256) {
        float4 w4 = ((const float4*)W)[i];
        int k = (i * 4) >> 6;
        int c = (i * 4) & 63;
        float* dr = &wsp[(k >> 1) * 128 + (k & 1)];
        dr[2 * c]       = w4.x;
        dr[2 * (c + 1)] = w4.y;
        dr[2 * (c + 2)] = w4.z;
        dr[2 * (c + 3)] = w4.w;
    }
}

// fp32-input GEMM (layer 1: A = x)
__global__ void __launch_bounds__(256) k_gemm_f32(const float* __restrict__ A,
                                                  const float* __restrict__ W,
                                                  __half* __restrict__ Out) {
    __shared__ float xs[128 * F_DIM];    // 32 KB
    __shared__ float wsp[32 * 128];      // 16 KB
    const int tid  = threadIdx.x;
    const size_t row0 = (size_t)blockIdx.x * 128;

    load_w(W, wsp, tid);
    {
        const float4* Ag  = (const float4*)(A + row0 * F_DIM);
        float4*       xs4 = (float4*)xs;
        #pragma unroll
        for (int i = 0; i < 8; i++)
            xs4[tid + i * 256] = Ag[tid + i * 256];
    }
    __syncthreads();
    gemm_core(xs, wsp, tid, row0, Out);
}

// fp16-input GEMM (layer 2: A = hidden)
__global__ void __launch_bounds__(256) k_gemm_f16(const __half* __restrict__ A,
                                                  const float* __restrict__ W,
                                                  __half* __restrict__ Out) {
    __shared__ float xs[128 * F_DIM];    // 32 KB (converted)
    __shared__ float wsp[32 * 128];      // 16 KB
    const int tid  = threadIdx.x;
    const size_t row0 = (size_t)blockIdx.x * 128;

    load_w(W, wsp, tid);
    {
        const float4* Ag = (const float4*)(A + row0 * F_DIM);  // 16B = 8 halves
        #pragma unroll
        for (int i = 0; i < 4; i++) {
            int idx = tid + i * 256;                // 0..1023
            float4 raw = Ag[idx];
            const __half2* hp = (const __half2*)&raw;
            float2 f0 = __half22float2(hp[0]);
            float2 f1 = __half22float2(hp[1]);
            float2 f2 = __half22float2(hp[2]);
            float2 f3 = __half22float2(hp[3]);
            float* dst = &xs[idx * 8];              // 8 consecutive floats
            ((float4*)dst)[0] = make_float4(f0.x, f0.y, f1.x, f1.y);
            ((float4*)dst)[1] = make_float4(f2.x, f2.y, f3.x, f3.y);
        }
    }
    __syncthreads();
    gemm_core(xs, wsp, tid, row0, Out);
}

// -------- aggregation over fp16 features: block = (node, 8 t-values);
// edge list in smem; split-lane LDG.64 gathers (2 edges / instruction);
// fp32 accumulate; bias(+relu); out fp16 (hidden) or fp32 (final). --------
__global__ void __launch_bounds__(256) k_agg(const __half* __restrict__ in,
                                             const float* __restrict__ bias,
                                             void* __restrict__ out,
                                             int do_relu, int out_fp16) {
    __shared__ int2 se[CAP];
    const int bid  = blockIdx.x;
    const int tg   = bid / N_NODES;            // 0..3
    const int node = bid - tg * N_NODES;
    const int tid  = threadIdx.x;

    int cnt = g_count[node];
    if (cnt > CAP) cnt = CAP;
    if (tid < cnt) se[tid] = g_csr[node * CAP + tid];
    __syncthreads();

    const int w    = tid >> 5;
    const int lane = tid & 31;
    const int half = lane >> 4;                // 0: edge e, 1: edge e+1
    const int hl   = lane & 15;                // 4-half slot within row
    const int t    = tg * 8 + w;

    // row = 64 halves = 16 ull; lane hl reads halves [4hl..4hl+3]
    const ull* base = (const ull*)(in + (size_t)t * (N_NODES * F_DIM)) + hl;

    ull a0 = 0ull, a1 = 0ull, a2 = 0ull, a3 = 0ull;
    int e = 0;
    for (; e + 7 < cnt; e += 8) {
        int2 s0 = se[e     + half];
        int2 s1 = se[e + 2 + half];
        int2 s2 = se[e + 4 + half];
        int2 s3 = se[e + 6 + half];
        ull v0 = __ldg(base + (unsigned)s0.x * 16u);
        ull v1 = __ldg(base + (unsigned)s1.x * 16u);
        ull v2 = __ldg(base + (unsigned)s2.x * 16u);
        ull v3 = __ldg(base + (unsigned)s3.x * 16u);
        float w0 = __int_as_float(s0.y), w1 = __int_as_float(s1.y);
        float w2 = __int_as_float(s2.y), w3 = __int_as_float(s3.y);
        {   const __half2* h = (const __half2*)&v0;
            float2 f0 = __half22float2(h[0]), f1 = __half22float2(h[1]);
            a0 = fma2(pack2(w0, w0), pack2(f0.x, f0.y), a0);
            a1 = fma2(pack2(w0, w0), pack2(f1.x, f1.y), a1); }
        {   const __half2* h = (const __half2*)&v1;
            float2 f0 = __half22float2(h[0]), f1 = __half22float2(h[1]);
            a2 = fma2(pack2(w1, w1), pack2(f0.x, f0.y), a2);
            a3 = fma2(pack2(w1, w1), pack2(f1.x, f1.y), a3); }
        {   const __half2* h = (const __half2*)&v2;
            float2 f0 = __half22float2(h[0]), f1 = __half22float2(h[1]);
            a0 = fma2(pack2(w2, w2), pack2(f0.x, f0.y), a0);
            a1 = fma2(pack2(w2, w2), pack2(f1.x, f1.y), a1); }
        {   const __half2* h = (const __half2*)&v3;
            float2 f0 = __half22float2(h[0]), f1 = __half22float2(h[1]);
            a2 = fma2(pack2(w3, w3), pack2(f0.x, f0.y), a2);
            a3 = fma2(pack2(w3, w3), pack2(f1.x, f1.y), a3); }
    }
    for (; e < cnt; e += 2) {
        int idx = e + half;
        if (idx < cnt) {
            int2 sn = se[idx];
            ull v = __ldg(base + (unsigned)sn.x * 16u);
            float ww = __int_as_float(sn.y);
            const __half2* h = (const __half2*)&v;
            float2 f0 = __half22float2(h[0]), f1 = __half22float2(h[1]);
            a0 = fma2(pack2(ww, ww), pack2(f0.x, f0.y), a0);
            a1 = fma2(pack2(ww, ww), pack2(f1.x, f1.y), a1);
        }
    }

    a0 = add2(a0, a2);
    a1 = add2(a1, a3);
    ull b0 = __shfl_down_sync(0xffffffffu, a0, 16);
    ull b1 = __shfl_down_sync(0xffffffffu, a1, 16);
    if (half == 0) {
        a0 = add2(a0, b0);
        a1 = add2(a1, b1);
        float2 p0 = unpack2(a0), p1 = unpack2(a1);
        float4 bv = __ldg((const float4*)bias + hl);
        float4 o = make_float4(p0.x + bv.x, p0.y + bv.y,
                               p1.x + bv.z, p1.y + bv.w);
        if (do_relu) {
            o.x = fmaxf(o.x, 0.f); o.y = fmaxf(o.y, 0.f);
            o.z = fmaxf(o.z, 0.f); o.w = fmaxf(o.w, 0.f);
        }
        const size_t row = (size_t)t * N_NODES + node;
        if (out_fp16) {
            ((ull*)out)[row * 16 + hl] = f4_to_h4(o.x, o.y, o.z, o.w);
        } else {
            ((float4*)out)[row * 16 + hl] = o;
        }
    }
}

// -------- launch: (A X) W == A (X W)  ->  GEMM first, bias+relu in agg --------
extern "C" void kernel_launch(void* const* d_in, const int* in_sizes, int n_in,
                              void* d_out, int out_size) {
    const float* x   = (const float*)d_in[0];
    const void*  ei  = d_in[1];
    const float* ew  = (const float*)d_in[2];
    const float* W1  = (const float*)d_in[3];
    const float* b1  = (const float*)d_in[4];
    const float* W2  = (const float*)d_in[5];
    const float* b2  = (const float*)d_in[6];
    float*       out = (float*)d_out;

    __half *h1 = nullptr, *h2 = nullptr;
    cudaGetSymbolAddress((void**)&h1, g_h1);
    cudaGetSymbolAddress((void**)&h2, g_h2);

    k_detect_init<<<(E_EDGES + 255) / 256, 256>>>(ei);       // 0
    k_hist       <<<(E_EDGES + 255) / 256, 256>>>(ei, ew);   // 1
    k_fill       <<<(E_EDGES + 255) / 256, 256>>>(ei, ew);   // 2

    // layer 1: h = relu(A (x W1) + b1)   [h stored fp16]
    k_gemm_f32<<<TN / 128, 256>>>(x, W1, h1);                // 3  (ncu target)
    k_agg     <<<N_NODES * (T_DIM / 8), 256>>>(h1, b1, h2, 1, 1);  // 4
    // layer 2: out = A (h W2) + b2       [final out fp32]
    k_gemm_f16<<<TN / 128, 256>>>(h2, W2, h1);               // 5
    k_agg     <<<N_NODES * (T_DIM / 8), 256>>>(h1, b2, out, 0, 0); // 6
}

// round 9
// speedup vs baseline: 1.8336x; 1.2774x over previous
#include <cuda_runtime.h>
#include <cuda_fp16.h>

#define T_DIM   32
#define N_NODES 10000
#define E_EDGES 160000
#define F_DIM   64
#define TN      (T_DIM * N_NODES)
#define CAP     64                      // max in-degree bucket capacity
#define SROW    72                      // padded smem row (halves) -> conflict-free ldmatrix

typedef unsigned long long ull;

// ---- packed f32x2 helpers ----
__device__ __forceinline__ ull pack2(float lo, float hi) {
    ull r; asm("mov.b64 %0, {%1, %2};" : "=l"(r) : "f"(lo), "f"(hi)); return r;
}
__device__ __forceinline__ float2 unpack2(ull v) {
    float2 r; asm("mov.b64 {%0, %1}, %2;" : "=f"(r.x), "=f"(r.y) : "l"(v)); return r;
}
__device__ __forceinline__ ull fma2(ull a, ull b, ull c) {
    ull d; asm("fma.rn.f32x2 %0, %1, %2, %3;" : "=l"(d) : "l"(a), "l"(b), "l"(c)); return d;
}
__device__ __forceinline__ ull add2(ull a, ull b) {
    ull d; asm("add.rn.f32x2 %0, %1, %2;" : "=l"(d) : "l"(a), "l"(b)); return d;
}
__device__ __forceinline__ ull f4_to_h4(float a, float b, float c, float d) {
    __half2 lo = __float22half2_rn(make_float2(a, b));
    __half2 hi = __float22half2_rn(make_float2(c, d));
    ull r;
    asm("mov.b64 %0, {%1, %2};" : "=l"(r)
        : "r"(*(unsigned*)&lo), "r"(*(unsigned*)&hi));
    return r;
}

// ---- tensor-core primitives ----
__device__ __forceinline__ unsigned smem_u32(const void* p) {
    return (unsigned)__cvta_generic_to_shared(p);
}
__device__ __forceinline__ void ldsm_x4(unsigned* r, unsigned addr) {
    asm volatile("ldmatrix.sync.aligned.m8n8.x4.shared.b16 {%0,%1,%2,%3}, [%4];"
        : "=r"(r[0]), "=r"(r[1]), "=r"(r[2]), "=r"(r[3]) : "r"(addr));
}
__device__ __forceinline__ void ldsm_x4_t(unsigned* r, unsigned addr) {
    asm volatile("ldmatrix.sync.aligned.m8n8.x4.trans.shared.b16 {%0,%1,%2,%3}, [%4];"
        : "=r"(r[0]), "=r"(r[1]), "=r"(r[2]), "=r"(r[3]) : "r"(addr));
}
__device__ __forceinline__ void mma_16816(float* c, const unsigned* a,
                                          unsigned b0, unsigned b1) {
    asm volatile("mma.sync.aligned.m16n8k16.row.col.f32.f16.f16.f32 "
        "{%0,%1,%2,%3}, {%4,%5,%6,%7}, {%8,%9}, {%0,%1,%2,%3};"
        : "+f"(c[0]), "+f"(c[1]), "+f"(c[2]), "+f"(c[3])
        : "r"(a[0]), "r"(a[1]), "r"(a[2]), "r"(a[3]), "r"(b0), "r"(b1));
}

// -------- device scratch --------
__device__ int    g_i64flag = 1;   // int64-detect: only ever written to 0
__device__ float  g_deg[N_NODES];
__device__ int    g_count[N_NODES];
__device__ int2   g_csr[N_NODES * CAP];
__device__ __half g_h1[(size_t)TN * F_DIM];           // 40.96 MB
__device__ __half g_h2[(size_t)TN * F_DIM];           // 40.96 MB

__device__ __forceinline__ int edge_src(const void* ei, int e) {
    return g_i64flag ? (int)((const long long*)ei)[e] : ((const int*)ei)[e];
}
__device__ __forceinline__ int edge_dst(const void* ei, int e) {
    return g_i64flag ? (int)((const long long*)ei)[E_EDGES + e]
                     : ((const int*)ei)[E_EDGES + e];
}

// -------- prep --------
__global__ void k_detect_init(const void* __restrict__ ei) {
    int e = blockIdx.x * blockDim.x + threadIdx.x;
    if (e < N_NODES) { g_deg[e] = 0.f; g_count[e] = 0; }
    if (e < E_EDGES) {
        long long v = ((const long long*)ei)[e];   // in-bounds for either dtype
        if (v < 0 || v >= N_NODES) g_i64flag = 0;
    }
}
__global__ void k_hist(const void* __restrict__ ei, const float* __restrict__ ew) {
    int e = blockIdx.x * blockDim.x + threadIdx.x;
    if (e < E_EDGES) atomicAdd(&g_deg[edge_dst(ei, e)], ew[e]);
}
__global__ void k_fill(const void* __restrict__ ei, const float* __restrict__ ew) {
    int e = blockIdx.x * blockDim.x + threadIdx.x;
    if (e < E_EDGES) {
        int src = edge_src(ei, e);
        int dst = edge_dst(ei, e);
        float ds = g_deg[src], dd = g_deg[dst];
        float is = (ds > 0.f) ? rsqrtf(ds) : 0.f;
        float id = (dd > 0.f) ? rsqrtf(dd) : 0.f;
        float nm = is * ew[e] * id;
        int pos = atomicAdd(&g_count[dst], 1);
        if (pos < CAP)
            g_csr[dst * CAP + pos] = make_int2(src, __float_as_int(nm));
    }
}

// -------- GEMM via HMMA: C[128x64] = A * W, fp16 in (converted), fp32 acc,
// fp16 out. Warp w computes rows [16w, 16w+16). ldmatrix + mma.m16n8k16. --------
__device__ __forceinline__ void gemm_mma_body(const void* __restrict__ A,
                                              const float* __restrict__ W,
                                              __half* __restrict__ Out,
                                              int a_is_fp32) {
    __shared__ __align__(16) __half sA[128 * SROW];   // 18 KB
    __shared__ __align__(16) __half sW[64 * SROW];    //  9 KB
    const int tid  = threadIdx.x;
    const size_t row0 = (size_t)blockIdx.x * 128;

    // ---- load W (64x64 fp32 -> fp16, padded) ----
    {
        int row = tid >> 2, c0 = (tid & 3) * 16;
        const float4* src = (const float4*)(W + row * 64 + c0);
        __half* dst = sW + row * SROW + c0;
        #pragma unroll
        for (int i = 0; i < 2; i++) {
            float4 u = src[2 * i], v = src[2 * i + 1];
            __half2 h0 = __float22half2_rn(make_float2(u.x, u.y));
            __half2 h1 = __float22half2_rn(make_float2(u.z, u.w));
            __half2 h2 = __float22half2_rn(make_float2(v.x, v.y));
            __half2 h3 = __float22half2_rn(make_float2(v.z, v.w));
            uint4 pk = make_uint4(*(unsigned*)&h0, *(unsigned*)&h1,
                                  *(unsigned*)&h2, *(unsigned*)&h3);
            *(uint4*)(dst + i * 8) = pk;
        }
    }
    // ---- load A tile (128x64 -> fp16, padded) ----
    {
        int row = tid >> 1, c0 = (tid & 1) * 32;
        __half* dst = sA + row * SROW + c0;
        if (a_is_fp32) {
            const float4* src = (const float4*)((const float*)A + (row0 + row) * 64 + c0);
            #pragma unroll
            for (int i = 0; i < 4; i++) {
                float4 u = src[2 * i], v = src[2 * i + 1];
                __half2 h0 = __float22half2_rn(make_float2(u.x, u.y));
                __half2 h1 = __float22half2_rn(make_float2(u.z, u.w));
                __half2 h2 = __float22half2_rn(make_float2(v.x, v.y));
                __half2 h3 = __float22half2_rn(make_float2(v.z, v.w));
                uint4 pk = make_uint4(*(unsigned*)&h0, *(unsigned*)&h1,
                                      *(unsigned*)&h2, *(unsigned*)&h3);
                *(uint4*)(dst + i * 8) = pk;
            }
        } else {
            const uint4* src = (const uint4*)((const __half*)A + (row0 + row) * 64 + c0);
            #pragma unroll
            for (int i = 0; i < 4; i++)
                *(uint4*)(dst + i * 8) = src[i];
        }
    }
    __syncthreads();

    const int w    = tid >> 5;
    const int lane = tid & 31;
    const int m0   = w * 16;
    const int grp  = lane >> 3;
    const int gr   = lane & 7;

    // per-thread ldmatrix base addresses
    const unsigned aBase = smem_u32(sA)
        + ((m0 + gr + (grp & 1) * 8) * SROW + (grp >> 1) * 8) * 2;
    const unsigned bBase = smem_u32(sW)
        + ((gr + (grp & 1) * 8) * SROW + (grp >> 1) * 8) * 2;

    float c[8][4];
    #pragma unroll
    for (int i = 0; i < 8; i++)
        #pragma unroll
        for (int j = 0; j < 4; j++) c[i][j] = 0.f;

    #pragma unroll
    for (int ks = 0; ks < 4; ks++) {          // k0 = 16*ks
        unsigned a[4];
        ldsm_x4(a, aBase + (16 * ks) * 2);
        #pragma unroll
        for (int ns = 0; ns < 4; ns++) {      // n0 = 16*ns
            unsigned b[4];
            ldsm_x4_t(b, bBase + (16 * ks * SROW + 16 * ns) * 2);
            mma_16816(c[2 * ns],     a, b[0], b[1]);
            mma_16816(c[2 * ns + 1], a, b[2], b[3]);
        }
    }

    // ---- epilogue: stage fp16 into own warp's sA rows (conflict-free), then
    // coalesced 16B global stores ----
    const int g = lane >> 2, t = lane & 3;
    #pragma unroll
    for (int nt = 0; nt < 8; nt++) {
        __half2 lo = __float22half2_rn(make_float2(c[nt][0], c[nt][1]));
        __half2 hi = __float22half2_rn(make_float2(c[nt][2], c[nt][3]));
        *(__half2*)(sA + (m0 + g)     * SROW + nt * 8 + 2 * t) = lo;
        *(__half2*)(sA + (m0 + 8 + g) * SROW + nt * 8 + 2 * t) = hi;
    }
    __syncwarp();
    {
        int row = m0 + (lane >> 1);
        int seg = (lane & 1) * 32;
        const uint4* s = (const uint4*)(sA + row * SROW + seg);
        uint4* d = (uint4*)(Out + (row0 + row) * 64 + seg);
        #pragma unroll
        for (int i = 0; i < 4; i++) d[i] = s[i];
    }
}

__global__ void __launch_bounds__(256) k_gemm_f32(const float* __restrict__ A,
                                                  const float* __restrict__ W,
                                                  __half* __restrict__ Out) {
    gemm_mma_body(A, W, Out, 1);
}
__global__ void __launch_bounds__(256) k_gemm_f16(const __half* __restrict__ A,
                                                  const float* __restrict__ W,
                                                  __half* __restrict__ Out) {
    gemm_mma_body(A, W, Out, 0);
}

// -------- aggregation over fp16 features (unchanged from R8) --------
__global__ void __launch_bounds__(256) k_agg(const __half* __restrict__ in,
                                             const float* __restrict__ bias,
                                             void* __restrict__ out,
                                             int do_relu, int out_fp16) {
    __shared__ int2 se[CAP];
    const int bid  = blockIdx.x;
    const int tg   = bid / N_NODES;            // 0..3
    const int node = bid - tg * N_NODES;
    const int tid  = threadIdx.x;

    int cnt = g_count[node];
    if (cnt > CAP) cnt = CAP;
    if (tid < cnt) se[tid] = g_csr[node * CAP + tid];
    __syncthreads();

    const int w    = tid >> 5;
    const int lane = tid & 31;
    const int half = lane >> 4;
    const int hl   = lane & 15;
    const int t    = tg * 8 + w;

    const ull* base = (const ull*)(in + (size_t)t * (N_NODES * F_DIM)) + hl;

    ull a0 = 0ull, a1 = 0ull, a2 = 0ull, a3 = 0ull;
    int e = 0;
    for (; e + 7 < cnt; e += 8) {
        int2 s0 = se[e     + half];
        int2 s1 = se[e + 2 + half];
        int2 s2 = se[e + 4 + half];
        int2 s3 = se[e + 6 + half];
        ull v0 = __ldg(base + (unsigned)s0.x * 16u);
        ull v1 = __ldg(base + (unsigned)s1.x * 16u);
        ull v2 = __ldg(base + (unsigned)s2.x * 16u);
        ull v3 = __ldg(base + (unsigned)s3.x * 16u);
        float w0 = __int_as_float(s0.y), w1 = __int_as_float(s1.y);
        float w2 = __int_as_float(s2.y), w3 = __int_as_float(s3.y);
        {   const __half2* h = (const __half2*)&v0;
            float2 f0 = __half22float2(h[0]), f1 = __half22float2(h[1]);
            a0 = fma2(pack2(w0, w0), pack2(f0.x, f0.y), a0);
            a1 = fma2(pack2(w0, w0), pack2(f1.x, f1.y), a1); }
        {   const __half2* h = (const __half2*)&v1;
            float2 f0 = __half22float2(h[0]), f1 = __half22float2(h[1]);
            a2 = fma2(pack2(w1, w1), pack2(f0.x, f0.y), a2);
            a3 = fma2(pack2(w1, w1), pack2(f1.x, f1.y), a3); }
        {   const __half2* h = (const __half2*)&v2;
            float2 f0 = __half22float2(h[0]), f1 = __half22float2(h[1]);
            a0 = fma2(pack2(w2, w2), pack2(f0.x, f0.y), a0);
            a1 = fma2(pack2(w2, w2), pack2(f1.x, f1.y), a1); }
        {   const __half2* h = (const __half2*)&v3;
            float2 f0 = __half22float2(h[0]), f1 = __half22float2(h[1]);
            a2 = fma2(pack2(w3, w3), pack2(f0.x, f0.y), a2);
            a3 = fma2(pack2(w3, w3), pack2(f1.x, f1.y), a3); }
    }
    for (; e < cnt; e += 2) {
        int idx = e + half;
        if (idx < cnt) {
            int2 sn = se[idx];
            ull v = __ldg(base + (unsigned)sn.x * 16u);
            float ww = __int_as_float(sn.y);
            const __half2* h = (const __half2*)&v;
            float2 f0 = __half22float2(h[0]), f1 = __half22float2(h[1]);
            a0 = fma2(pack2(ww, ww), pack2(f0.x, f0.y), a0);
            a1 = fma2(pack2(ww, ww), pack2(f1.x, f1.y), a1);
        }
    }

    a0 = add2(a0, a2);
    a1 = add2(a1, a3);
    ull b0 = __shfl_down_sync(0xffffffffu, a0, 16);
    ull b1 = __shfl_down_sync(0xffffffffu, a1, 16);
    if (half == 0) {
        a0 = add2(a0, b0);
        a1 = add2(a1, b1);
        float2 p0 = unpack2(a0), p1 = unpack2(a1);
        float4 bv = __ldg((const float4*)bias + hl);
        float4 o = make_float4(p0.x + bv.x, p0.y + bv.y,
                               p1.x + bv.z, p1.y + bv.w);
        if (do_relu) {
            o.x = fmaxf(o.x, 0.f); o.y = fmaxf(o.y, 0.f);
            o.z = fmaxf(o.z, 0.f); o.w = fmaxf(o.w, 0.f);
        }
        const size_t row = (size_t)t * N_NODES + node;
        if (out_fp16) {
            ((ull*)out)[row * 16 + hl] = f4_to_h4(o.x, o.y, o.z, o.w);
        } else {
            ((float4*)out)[row * 16 + hl] = o;
        }
    }
}

// -------- launch: (A X) W == A (X W)  ->  GEMM first, bias+relu in agg --------
extern "C" void kernel_launch(void* const* d_in, const int* in_sizes, int n_in,
                              void* d_out, int out_size) {
    const float* x   = (const float*)d_in[0];
    const void*  ei  = d_in[1];
    const float* ew  = (const float*)d_in[2];
    const float* W1  = (const float*)d_in[3];
    const float* b1  = (const float*)d_in[4];
    const float* W2  = (const float*)d_in[5];
    const float* b2  = (const float*)d_in[6];
    float*       out = (float*)d_out;

    __half *h1 = nullptr, *h2 = nullptr;
    cudaGetSymbolAddress((void**)&h1, g_h1);
    cudaGetSymbolAddress((void**)&h2, g_h2);

    k_detect_init<<<(E_EDGES + 255) / 256, 256>>>(ei);       // 0
    k_hist       <<<(E_EDGES + 255) / 256, 256>>>(ei, ew);   // 1
    k_fill       <<<(E_EDGES + 255) / 256, 256>>>(ei, ew);   // 2

    // layer 1: h = relu(A (x W1) + b1)   [h stored fp16]
    k_gemm_f32<<<TN / 128, 256>>>(x, W1, h1);                // 3  (ncu target)
    k_agg     <<<N_NODES * (T_DIM / 8), 256>>>(h1, b1, h2, 1, 1);  // 4
    // layer 2: out = A (h W2) + b2       [final out fp32]
    k_gemm_f16<<<TN / 128, 256>>>(h2, W2, h1);               // 5
    k_agg     <<<N_NODES * (T_DIM / 8), 256>>>(h1, b2, out, 0, 0); // 6
}